// round 3
// baseline (speedup 1.0000x reference)
#include <cuda_runtime.h>
#include <cstdint>

// ---------------------------------------------------------------------------
// FineSubMatching — fused fp32 implementation with G = P^T P trick.
//   sim = feat0 @ G @ feat1^T   with G = (P^T P) * (1/C) * (1/TEMPERATURE)
//   conf[l,s] = exp(2*sim - rmax_l - cmax_s) * rinv_l * cinv_s
//   argmax (first-occurrence tie-break), threshold, MLP on selected features.
// Output layout (fp32): mkpts0[M,2] | mkpts1[M,2] | mconf[M] | conf[M,64,64]
// ---------------------------------------------------------------------------

#define STR 68          // padded smem row stride (floats)
#define MMAX 8192

__device__ float g_G[64 * 64];
__device__ int   g_idx[MMAX];

// Packed dual-FMA helper: acc(2xf32) += a2 * b2, elementwise.
// sm_100+ uses the f32x2 pipe (2x rate); fallback is two scalar FFMA.
__device__ __forceinline__ void fma2(unsigned long long& acc,
                                     unsigned long long a2,
                                     unsigned long long b2) {
#if defined(__CUDA_ARCH__) && (__CUDA_ARCH__ >= 1000)
    asm("fma.rn.f32x2 %0, %1, %2, %0;" : "+l"(acc) : "l"(a2), "l"(b2));
#else
    float alo, ahi, blo, bhi, clo, chi;
    asm("mov.b64 {%0,%1},%2;" : "=f"(alo), "=f"(ahi) : "l"(a2));
    asm("mov.b64 {%0,%1},%2;" : "=f"(blo), "=f"(bhi) : "l"(b2));
    asm("mov.b64 {%0,%1},%2;" : "=f"(clo), "=f"(chi) : "l"(acc));
    clo = fmaf(alo, blo, clo);
    chi = fmaf(ahi, bhi, chi);
    asm("mov.b64 %0,{%1,%2};" : "=l"(acc) : "f"(clo), "f"(chi));
#endif
}

__device__ __forceinline__ unsigned long long pack2(float lo, float hi) {
    unsigned long long r;
    asm("mov.b64 %0,{%1,%2};" : "=l"(r) : "f"(lo), "f"(hi));
    return r;
}
__device__ __forceinline__ float2 unpack2(unsigned long long v) {
    float2 r;
    asm("mov.b64 {%0,%1},%2;" : "=f"(r.x), "=f"(r.y) : "l"(v));
    return r;
}

// ---------------------------------------------------------------------------
// prep: G[c][d] = sum_k P[k][c]*P[k][d] * (1/64) * (1/0.1)
// ---------------------------------------------------------------------------
__global__ void prep_kernel(const float* __restrict__ P) {
    __shared__ float sP[64 * 65];
    int tid = threadIdx.x;
#pragma unroll
    for (int it = 0; it < 16; ++it) {
        int e = tid + 256 * it;
        sP[(e >> 6) * 65 + (e & 63)] = P[e];
    }
    __syncthreads();
    int e = blockIdx.x * 256 + tid;      // 0..4095
    int c = e >> 6, d = e & 63;
    float acc = 0.f;
#pragma unroll 16
    for (int k = 0; k < 64; ++k)
        acc += sP[k * 65 + c] * sP[k * 65 + d];
    g_G[e] = acc * 0.15625f;             // (1/64) * 10
}

// ---------------------------------------------------------------------------
// main: per-row GEMMs + dual softmax + conf store + argmax
// ---------------------------------------------------------------------------
__global__ __launch_bounds__(256, 2) void main_kernel(
    const float* __restrict__ f0g, const float* __restrict__ f1g,
    float* __restrict__ out_conf, float* __restrict__ out_mconf)
{
    extern __shared__ float sm[];
    float* sA  = sm;                 // feat0 [l][c]  -> later sim [l][s]
    float* sBT = sm + 64 * STR;      // feat1^T [d][s]
    float* sG  = sm + 2 * 64 * STR;  // G [c][d]
    float* sT  = sm + 3 * 64 * STR;  // staging feat1 (stride 65) -> later t [l][d]

    __shared__ float rmax_s[64], rinv_s[64], cmax_s[64], cinv_s[64];
    __shared__ float redv[256];
    __shared__ int   redi[256];

    int n = blockIdx.x, tid = threadIdx.x;
    const float* F0 = f0g + (size_t)n * 4096;
    const float* F1 = f1g + (size_t)n * 4096;

    // ---- load tiles (coalesced global, conflict-free smem) ----
#pragma unroll
    for (int it = 0; it < 16; ++it) {
        int e = tid + 256 * it;
        int r = e >> 6, c = e & 63;
        sA[r * STR + c] = F0[e];
        sG[r * STR + c] = g_G[e];
        sT[r * 65 + c]  = F1[e];     // staging for transpose (stride 65: bank-clean)
    }
    __syncthreads();
#pragma unroll
    for (int it = 0; it < 16; ++it) {
        int e = tid + 256 * it;
        int d = e >> 6, s = e & 63;
        sBT[d * STR + s] = sT[s * 65 + d];
    }
    __syncthreads();

    int tx = tid & 15, ty = tid >> 4;
    int r0 = ty * 4, c0 = tx * 4;

    // ---- GEMM1: t = A @ G   (4x4 thread tile, packed dual-FMA) ----
    unsigned long long acc[4][2];
#pragma unroll
    for (int i = 0; i < 4; ++i) { acc[i][0] = 0ull; acc[i][1] = 0ull; }

#pragma unroll 8
    for (int c = 0; c < 64; ++c) {
        float4 bq = *reinterpret_cast<const float4*>(&sG[c * STR + c0]);
        unsigned long long b0 = pack2(bq.x, bq.y);
        unsigned long long b1 = pack2(bq.z, bq.w);
#pragma unroll
        for (int i = 0; i < 4; ++i) {
            float a = sA[(r0 + i) * STR + c];
            unsigned long long a2 = pack2(a, a);
            fma2(acc[i][0], a2, b0);
            fma2(acc[i][1], a2, b1);
        }
    }
    // store t into sT (all stride-65 staging readers passed the last barrier)
#pragma unroll
    for (int i = 0; i < 4; ++i)
#pragma unroll
        for (int jp = 0; jp < 2; ++jp)
            *reinterpret_cast<float2*>(&sT[(r0 + i) * STR + c0 + 2 * jp]) =
                unpack2(acc[i][jp]);
    __syncthreads();

    // ---- GEMM2: sim = t @ feat1^T ----
#pragma unroll
    for (int i = 0; i < 4; ++i) { acc[i][0] = 0ull; acc[i][1] = 0ull; }

#pragma unroll 8
    for (int d = 0; d < 64; ++d) {
        float4 bq = *reinterpret_cast<const float4*>(&sBT[d * STR + c0]);
        unsigned long long b0 = pack2(bq.x, bq.y);
        unsigned long long b1 = pack2(bq.z, bq.w);
#pragma unroll
        for (int i = 0; i < 4; ++i) {
            float a = sT[(r0 + i) * STR + d];
            unsigned long long a2 = pack2(a, a);
            fma2(acc[i][0], a2, b0);
            fma2(acc[i][1], a2, b1);
        }
    }
    // store sim into sA (no concurrent sA readers; tiles are exclusive)
#pragma unroll
    for (int i = 0; i < 4; ++i)
#pragma unroll
        for (int jp = 0; jp < 2; ++jp)
            *reinterpret_cast<float2*>(&sA[(r0 + i) * STR + c0 + 2 * jp]) =
                unpack2(acc[i][jp]);
    __syncthreads();

    const float* sS = sA;

    // ---- row pass (softmax over s for each l): rmax, rinv ----
    {
        int l = tid >> 2, q = tid & 3;
        float m = -1e30f;
#pragma unroll
        for (int k = 0; k < 16; ++k)
            m = fmaxf(m, sS[l * STR + q + 4 * k]);
        redv[tid] = m;
        __syncthreads();
        if (tid < 64)
            rmax_s[tid] = fmaxf(fmaxf(redv[4 * tid], redv[4 * tid + 1]),
                                fmaxf(redv[4 * tid + 2], redv[4 * tid + 3]));
        __syncthreads();
        float rm = rmax_s[l];
        float s = 0.f;
#pragma unroll
        for (int k = 0; k < 16; ++k)
            s += __expf(sS[l * STR + q + 4 * k] - rm);
        redv[tid] = s;
        __syncthreads();
        if (tid < 64)
            rinv_s[tid] = 1.0f / (redv[4 * tid] + redv[4 * tid + 1] +
                                  redv[4 * tid + 2] + redv[4 * tid + 3]);
        __syncthreads();
    }

    // ---- col pass (softmax over l for each s): cmax, cinv ----
    {
        int s = tid & 63, q = tid >> 6;
        float m = -1e30f;
#pragma unroll
        for (int k = 0; k < 16; ++k)
            m = fmaxf(m, sS[(16 * q + k) * STR + s]);
        redv[tid] = m;
        __syncthreads();
        if (tid < 64)
            cmax_s[tid] = fmaxf(fmaxf(redv[tid], redv[tid + 64]),
                                fmaxf(redv[tid + 128], redv[tid + 192]));
        __syncthreads();
        float cm = cmax_s[s];
        float sum = 0.f;
#pragma unroll
        for (int k = 0; k < 16; ++k)
            sum += __expf(sS[(16 * q + k) * STR + s] - cm);
        redv[tid] = sum;
        __syncthreads();
        if (tid < 64)
            cinv_s[tid] = 1.0f / (redv[tid] + redv[tid + 64] +
                                  redv[tid + 128] + redv[tid + 192]);
        __syncthreads();
    }

    // ---- conf + coalesced store + argmax (first-occurrence tie-break) ----
    float best = -1.f;
    int bidx = 0;
    float* OC = out_conf + (size_t)n * 4096;
#pragma unroll
    for (int m = 0; m < 16; ++m) {
        int flat = tid + 256 * m;
        int l = flat >> 6, s = flat & 63;
        float v = __expf(2.0f * sS[l * STR + s] - rmax_s[l] - cmax_s[s]) *
                  rinv_s[l] * cinv_s[s];
        OC[flat] = v;
        if (v > best) { best = v; bidx = flat; }
    }
#pragma unroll
    for (int off = 16; off > 0; off >>= 1) {
        float ov = __shfl_down_sync(0xffffffffu, best, off);
        int   oi = __shfl_down_sync(0xffffffffu, bidx, off);
        if (ov > best || (ov == best && oi < bidx)) { best = ov; bidx = oi; }
    }
    if ((tid & 31) == 0) { redv[tid >> 5] = best; redi[tid >> 5] = bidx; }
    __syncthreads();
    if (tid == 0) {
        float b = redv[0]; int bi = redi[0];
#pragma unroll
        for (int w = 1; w < 8; ++w)
            if (redv[w] > b || (redv[w] == b && redi[w] < bi)) { b = redv[w]; bi = redi[w]; }
        out_mconf[n] = (b > 0.1f) ? b : 0.f;
        g_idx[n] = bi;
    }
}

// ---------------------------------------------------------------------------
// mlp: gather selected features, h = relu(cat @ W1^T), delta = tanh(h @ W2^T)*0.5,
// coordinate arithmetic. 32 rows per block; W1 cached in smem.
// ---------------------------------------------------------------------------
__global__ __launch_bounds__(256) void mlp_kernel(
    const float* __restrict__ f0g, const float* __restrict__ f1g,
    const float* __restrict__ w1, const float* __restrict__ w2,
    const int* __restrict__ iids, const int* __restrict__ jids,
    float* __restrict__ mk0, float* __restrict__ mk1, int M)
{
    extern __shared__ float w1s[];           // 128 * 129
    __shared__ float w2s[4 * 128];
    __shared__ float cat[128];
    __shared__ float hpart[256];
    __shared__ float hbuf[128];
    __shared__ float ds[4];

    int tid = threadIdx.x;
#pragma unroll
    for (int it = 0; it < 64; ++it) {
        int e = tid + 256 * it;
        w1s[(e >> 7) * 129 + (e & 127)] = w1[e];
    }
#pragma unroll
    for (int it = 0; it < 2; ++it)
        w2s[tid + 256 * it] = w2[tid + 256 * it];
    __syncthreads();

    for (int r = 0; r < 32; ++r) {
        int n = blockIdx.x * 32 + r;
        if (n >= M) break;
        int idx = g_idx[n];
        int il = idx >> 6, jl = idx & 63;

        if (tid < 128)
            cat[tid] = (tid < 64) ? f0g[(size_t)n * 4096 + il * 64 + tid]
                                  : f1g[(size_t)n * 4096 + jl * 64 + (tid - 64)];
        __syncthreads();

        {
            int j = tid & 127, half = tid >> 7;
            const float* wr = &w1s[j * 129 + half * 64];
            const float* cr = &cat[half * 64];
            float a = 0.f;
#pragma unroll 16
            for (int k = 0; k < 64; ++k)
                a += cr[k] * wr[k];
            hpart[half * 128 + j] = a;
        }
        __syncthreads();
        if (tid < 128)
            hbuf[tid] = fmaxf(hpart[tid] + hpart[128 + tid], 0.f);
        __syncthreads();

        if (tid < 128) {
            int o = tid >> 5, lane = tid & 31;
            const float* wrow = &w2s[o * 128];
            float p = hbuf[lane] * wrow[lane] +
                      hbuf[lane + 32] * wrow[lane + 32] +
                      hbuf[lane + 64] * wrow[lane + 64] +
                      hbuf[lane + 96] * wrow[lane + 96];
#pragma unroll
            for (int off = 16; off > 0; off >>= 1)
                p += __shfl_down_sync(0xffffffffu, p, off);
            if (lane == 0) ds[o] = tanhf(p) * 0.5f;
        }
        __syncthreads();

        if (tid == 0) {
            int ii = iids[n], jj = jids[n];
            float b0x = (float)((il & 7) + (ii % 160) * 4);
            float b0y = (float)((il >> 3) + (ii / 160) * 4);
            float b1x = (float)((jl & 7) + (jj % 160) * 4);
            float b1y = (float)((jl >> 3) + (jj / 160) * 4);
            mk0[2 * n]     = (b0x + ds[0]) * 2.f;
            mk0[2 * n + 1] = (b0y + ds[1]) * 2.f;
            mk1[2 * n]     = (b1x + ds[2]) * 2.f;
            mk1[2 * n + 1] = (b1y + ds[3]) * 2.f;
        }
        __syncthreads();
    }
}

// ---------------------------------------------------------------------------
// launch
// ---------------------------------------------------------------------------
extern "C" void kernel_launch(void* const* d_in, const int* in_sizes, int n_in,
                              void* d_out, int out_size)
{
    const float* f0 = (const float*)d_in[0];
    const float* f1 = (const float*)d_in[1];
    const float* pw = (const float*)d_in[2];
    const float* w1 = (const float*)d_in[3];
    const float* w2 = (const float*)d_in[4];
    const int*   ii = (const int*)d_in[6];
    const int*   jj = (const int*)d_in[7];
    int M = in_sizes[5];                  // b_ids element count
    if (M > MMAX) M = MMAX;

    float* out     = (float*)d_out;
    float* mk0     = out;                 // [M,2]
    float* mk1     = out + 2 * M;         // [M,2]
    float* mconf   = out + 4 * M;         // [M]
    float* conf    = out + 5 * M;         // [M,64,64]

    const int MAIN_SMEM = 4 * 64 * STR * (int)sizeof(float);   // 69632
    const int MLP_SMEM  = 128 * 129 * (int)sizeof(float);      // 66048
    cudaFuncSetAttribute(main_kernel, cudaFuncAttributeMaxDynamicSharedMemorySize, MAIN_SMEM);
    cudaFuncSetAttribute(mlp_kernel,  cudaFuncAttributeMaxDynamicSharedMemorySize, MLP_SMEM);

    prep_kernel<<<16, 256>>>(pw);
    main_kernel<<<M, 256, MAIN_SMEM>>>(f0, f1, conf, mconf);
    mlp_kernel<<<(M + 31) / 32, 256, MLP_SMEM>>>(f0, f1, w1, w2, ii, jj, mk0, mk1, M);
}

// round 5
// speedup vs baseline: 1.0004x; 1.0004x over previous
#include <cuda_runtime.h>
#include <cstdint>

// ---------------------------------------------------------------------------
// FineSubMatching — fused fp32 implementation with G = P^T P trick.
//   sim = feat0 @ G @ feat1^T   with G = (P^T P) * (1/C) * (1/TEMPERATURE)
//   conf[l,s] = exp(2*sim - rmax_l - cmax_s) * rinv_l * cinv_s
//   argmax (first-occurrence tie-break), threshold, MLP on selected features.
// Output layout (fp32): mkpts0[M,2] | mkpts1[M,2] | mconf[M] | conf[M,64,64]
// ---------------------------------------------------------------------------

#define STR 68          // padded smem row stride (floats)
#define MMAX 8192

__device__ float g_G[64 * 64];
__device__ int   g_idx[MMAX];

// Packed dual-FMA helper: acc(2xf32) += a2 * b2, elementwise.
// sm_100+ uses the f32x2 pipe (2x rate); fallback is two scalar FFMA.
__device__ __forceinline__ void fma2(unsigned long long& acc,
                                     unsigned long long a2,
                                     unsigned long long b2) {
#if defined(__CUDA_ARCH__) && (__CUDA_ARCH__ >= 1000)
    asm("fma.rn.f32x2 %0, %1, %2, %0;" : "+l"(acc) : "l"(a2), "l"(b2));
#else
    float alo, ahi, blo, bhi, clo, chi;
    asm("mov.b64 {%0,%1},%2;" : "=f"(alo), "=f"(ahi) : "l"(a2));
    asm("mov.b64 {%0,%1},%2;" : "=f"(blo), "=f"(bhi) : "l"(b2));
    asm("mov.b64 {%0,%1},%2;" : "=f"(clo), "=f"(chi) : "l"(acc));
    clo = fmaf(alo, blo, clo);
    chi = fmaf(ahi, bhi, chi);
    asm("mov.b64 %0,{%1,%2};" : "=l"(acc) : "f"(clo), "f"(chi));
#endif
}

__device__ __forceinline__ unsigned long long pack2(float lo, float hi) {
    unsigned long long r;
    asm("mov.b64 %0,{%1,%2};" : "=l"(r) : "f"(lo), "f"(hi));
    return r;
}
__device__ __forceinline__ float2 unpack2(unsigned long long v) {
    float2 r;
    asm("mov.b64 {%0,%1},%2;" : "=f"(r.x), "=f"(r.y) : "l"(v));
    return r;
}

// ---------------------------------------------------------------------------
// prep: G[c][d] = sum_k P[k][c]*P[k][d] * (1/64) * (1/0.1)
// ---------------------------------------------------------------------------
__global__ void prep_kernel(const float* __restrict__ P) {
    __shared__ float sP[64 * 65];
    int tid = threadIdx.x;
#pragma unroll
    for (int it = 0; it < 16; ++it) {
        int e = tid + 256 * it;
        sP[(e >> 6) * 65 + (e & 63)] = P[e];
    }
    __syncthreads();
    int e = blockIdx.x * 256 + tid;      // 0..4095
    int c = e >> 6, d = e & 63;
    float acc = 0.f;
#pragma unroll 16
    for (int k = 0; k < 64; ++k)
        acc += sP[k * 65 + c] * sP[k * 65 + d];
    g_G[e] = acc * 0.15625f;             // (1/64) * 10
}

// ---------------------------------------------------------------------------
// main: per-row GEMMs + dual softmax + conf store + argmax
// ---------------------------------------------------------------------------
__global__ __launch_bounds__(256, 2) void main_kernel(
    const float* __restrict__ f0g, const float* __restrict__ f1g,
    float* __restrict__ out_conf, float* __restrict__ out_mconf)
{
    extern __shared__ float sm[];
    float* sA  = sm;                 // feat0 [l][c]  -> later sim [l][s]
    float* sBT = sm + 64 * STR;      // feat1^T [d][s]
    float* sG  = sm + 2 * 64 * STR;  // G [c][d]
    float* sT  = sm + 3 * 64 * STR;  // staging feat1 (stride 65) -> later t [l][d]

    __shared__ float rmax_s[64], rinv_s[64], cmax_s[64], cinv_s[64];
    __shared__ float redv[256];
    __shared__ int   redi[256];

    int n = blockIdx.x, tid = threadIdx.x;
    const float* F0 = f0g + (size_t)n * 4096;
    const float* F1 = f1g + (size_t)n * 4096;

    // ---- load tiles (coalesced global, conflict-free smem) ----
#pragma unroll
    for (int it = 0; it < 16; ++it) {
        int e = tid + 256 * it;
        int r = e >> 6, c = e & 63;
        sA[r * STR + c] = F0[e];
        sG[r * STR + c] = g_G[e];
        sT[r * 65 + c]  = F1[e];     // staging for transpose (stride 65: bank-clean)
    }
    __syncthreads();
#pragma unroll
    for (int it = 0; it < 16; ++it) {
        int e = tid + 256 * it;
        int d = e >> 6, s = e & 63;
        sBT[d * STR + s] = sT[s * 65 + d];
    }
    __syncthreads();

    int tx = tid & 15, ty = tid >> 4;
    int r0 = ty * 4, c0 = tx * 4;

    // ---- GEMM1: t = A @ G   (4x4 thread tile, packed dual-FMA) ----
    unsigned long long acc[4][2];
#pragma unroll
    for (int i = 0; i < 4; ++i) { acc[i][0] = 0ull; acc[i][1] = 0ull; }

#pragma unroll 8
    for (int c = 0; c < 64; ++c) {
        float4 bq = *reinterpret_cast<const float4*>(&sG[c * STR + c0]);
        unsigned long long b0 = pack2(bq.x, bq.y);
        unsigned long long b1 = pack2(bq.z, bq.w);
#pragma unroll
        for (int i = 0; i < 4; ++i) {
            float a = sA[(r0 + i) * STR + c];
            unsigned long long a2 = pack2(a, a);
            fma2(acc[i][0], a2, b0);
            fma2(acc[i][1], a2, b1);
        }
    }
    // store t into sT (all stride-65 staging readers passed the last barrier)
#pragma unroll
    for (int i = 0; i < 4; ++i)
#pragma unroll
        for (int jp = 0; jp < 2; ++jp)
            *reinterpret_cast<float2*>(&sT[(r0 + i) * STR + c0 + 2 * jp]) =
                unpack2(acc[i][jp]);
    __syncthreads();

    // ---- GEMM2: sim = t @ feat1^T ----
#pragma unroll
    for (int i = 0; i < 4; ++i) { acc[i][0] = 0ull; acc[i][1] = 0ull; }

#pragma unroll 8
    for (int d = 0; d < 64; ++d) {
        float4 bq = *reinterpret_cast<const float4*>(&sBT[d * STR + c0]);
        unsigned long long b0 = pack2(bq.x, bq.y);
        unsigned long long b1 = pack2(bq.z, bq.w);
#pragma unroll
        for (int i = 0; i < 4; ++i) {
            float a = sT[(r0 + i) * STR + d];
            unsigned long long a2 = pack2(a, a);
            fma2(acc[i][0], a2, b0);
            fma2(acc[i][1], a2, b1);
        }
    }
    // store sim into sA (no concurrent sA readers; tiles are exclusive)
#pragma unroll
    for (int i = 0; i < 4; ++i)
#pragma unroll
        for (int jp = 0; jp < 2; ++jp)
            *reinterpret_cast<float2*>(&sA[(r0 + i) * STR + c0 + 2 * jp]) =
                unpack2(acc[i][jp]);
    __syncthreads();

    const float* sS = sA;

    // ---- row pass (softmax over s for each l): rmax, rinv ----
    {
        int l = tid >> 2, q = tid & 3;
        float m = -1e30f;
#pragma unroll
        for (int k = 0; k < 16; ++k)
            m = fmaxf(m, sS[l * STR + q + 4 * k]);
        redv[tid] = m;
        __syncthreads();
        if (tid < 64)
            rmax_s[tid] = fmaxf(fmaxf(redv[4 * tid], redv[4 * tid + 1]),
                                fmaxf(redv[4 * tid + 2], redv[4 * tid + 3]));
        __syncthreads();
        float rm = rmax_s[l];
        float s = 0.f;
#pragma unroll
        for (int k = 0; k < 16; ++k)
            s += __expf(sS[l * STR + q + 4 * k] - rm);
        redv[tid] = s;
        __syncthreads();
        if (tid < 64)
            rinv_s[tid] = 1.0f / (redv[4 * tid] + redv[4 * tid + 1] +
                                  redv[4 * tid + 2] + redv[4 * tid + 3]);
        __syncthreads();
    }

    // ---- col pass (softmax over l for each s): cmax, cinv ----
    {
        int s = tid & 63, q = tid >> 6;
        float m = -1e30f;
#pragma unroll
        for (int k = 0; k < 16; ++k)
            m = fmaxf(m, sS[(16 * q + k) * STR + s]);
        redv[tid] = m;
        __syncthreads();
        if (tid < 64)
            cmax_s[tid] = fmaxf(fmaxf(redv[tid], redv[tid + 64]),
                                fmaxf(redv[tid + 128], redv[tid + 192]));
        __syncthreads();
        float cm = cmax_s[s];
        float sum = 0.f;
#pragma unroll
        for (int k = 0; k < 16; ++k)
            sum += __expf(sS[(16 * q + k) * STR + s] - cm);
        redv[tid] = sum;
        __syncthreads();
        if (tid < 64)
            cinv_s[tid] = 1.0f / (redv[tid] + redv[tid + 64] +
                                  redv[tid + 128] + redv[tid + 192]);
        __syncthreads();
    }

    // ---- conf + coalesced store + argmax (first-occurrence tie-break) ----
    float best = -1.f;
    int bidx = 0;
    float* OC = out_conf + (size_t)n * 4096;
#pragma unroll
    for (int m = 0; m < 16; ++m) {
        int flat = tid + 256 * m;
        int l = flat >> 6, s = flat & 63;
        float v = __expf(2.0f * sS[l * STR + s] - rmax_s[l] - cmax_s[s]) *
                  rinv_s[l] * cinv_s[s];
        OC[flat] = v;
        if (v > best) { best = v; bidx = flat; }
    }
#pragma unroll
    for (int off = 16; off > 0; off >>= 1) {
        float ov = __shfl_down_sync(0xffffffffu, best, off);
        int   oi = __shfl_down_sync(0xffffffffu, bidx, off);
        if (ov > best || (ov == best && oi < bidx)) { best = ov; bidx = oi; }
    }
    if ((tid & 31) == 0) { redv[tid >> 5] = best; redi[tid >> 5] = bidx; }
    __syncthreads();
    if (tid == 0) {
        float b = redv[0]; int bi = redi[0];
#pragma unroll
        for (int w = 1; w < 8; ++w)
            if (redv[w] > b || (redv[w] == b && redi[w] < bi)) { b = redv[w]; bi = redi[w]; }
        out_mconf[n] = (b > 0.1f) ? b : 0.f;
        g_idx[n] = bi;
    }
}

// ---------------------------------------------------------------------------
// mlp: gather selected features, h = relu(cat @ W1^T), delta = tanh(h @ W2^T)*0.5,
// coordinate arithmetic. 32 rows per block; W1 cached in smem.
// ---------------------------------------------------------------------------
__global__ __launch_bounds__(256) void mlp_kernel(
    const float* __restrict__ f0g, const float* __restrict__ f1g,
    const float* __restrict__ w1, const float* __restrict__ w2,
    const int* __restrict__ iids, const int* __restrict__ jids,
    float* __restrict__ mk0, float* __restrict__ mk1, int M)
{
    extern __shared__ float w1s[];           // 128 * 129
    __shared__ float w2s[4 * 128];
    __shared__ float cat[128];
    __shared__ float hpart[256];
    __shared__ float hbuf[128];
    __shared__ float ds[4];

    int tid = threadIdx.x;
#pragma unroll
    for (int it = 0; it < 64; ++it) {
        int e = tid + 256 * it;
        w1s[(e >> 7) * 129 + (e & 127)] = w1[e];
    }
#pragma unroll
    for (int it = 0; it < 2; ++it)
        w2s[tid + 256 * it] = w2[tid + 256 * it];
    __syncthreads();

    for (int r = 0; r < 32; ++r) {
        int n = blockIdx.x * 32 + r;
        if (n >= M) break;
        int idx = g_idx[n];
        int il = idx >> 6, jl = idx & 63;

        if (tid < 128)
            cat[tid] = (tid < 64) ? f0g[(size_t)n * 4096 + il * 64 + tid]
                                  : f1g[(size_t)n * 4096 + jl * 64 + (tid - 64)];
        __syncthreads();

        {
            int j = tid & 127, half = tid >> 7;
            const float* wr = &w1s[j * 129 + half * 64];
            const float* cr = &cat[half * 64];
            float a = 0.f;
#pragma unroll 16
            for (int k = 0; k < 64; ++k)
                a += cr[k] * wr[k];
            hpart[half * 128 + j] = a;
        }
        __syncthreads();
        if (tid < 128)
            hbuf[tid] = fmaxf(hpart[tid] + hpart[128 + tid], 0.f);
        __syncthreads();

        if (tid < 128) {
            int o = tid >> 5, lane = tid & 31;
            const float* wrow = &w2s[o * 128];
            float p = hbuf[lane] * wrow[lane] +
                      hbuf[lane + 32] * wrow[lane + 32] +
                      hbuf[lane + 64] * wrow[lane + 64] +
                      hbuf[lane + 96] * wrow[lane + 96];
#pragma unroll
            for (int off = 16; off > 0; off >>= 1)
                p += __shfl_down_sync(0xffffffffu, p, off);
            if (lane == 0) ds[o] = tanhf(p) * 0.5f;
        }
        __syncthreads();

        if (tid == 0) {
            int ii = iids[n], jj = jids[n];
            float b0x = (float)((il & 7) + (ii % 160) * 4);
            float b0y = (float)((il >> 3) + (ii / 160) * 4);
            float b1x = (float)((jl & 7) + (jj % 160) * 4);
            float b1y = (float)((jl >> 3) + (jj / 160) * 4);
            mk0[2 * n]     = (b0x + ds[0]) * 2.f;
            mk0[2 * n + 1] = (b0y + ds[1]) * 2.f;
            mk1[2 * n]     = (b1x + ds[2]) * 2.f;
            mk1[2 * n + 1] = (b1y + ds[3]) * 2.f;
        }
        __syncthreads();
    }
}

// ---------------------------------------------------------------------------
// launch
// ---------------------------------------------------------------------------
extern "C" void kernel_launch(void* const* d_in, const int* in_sizes, int n_in,
                              void* d_out, int out_size)
{
    const float* f0 = (const float*)d_in[0];
    const float* f1 = (const float*)d_in[1];
    const float* pw = (const float*)d_in[2];
    const float* w1 = (const float*)d_in[3];
    const float* w2 = (const float*)d_in[4];
    const int*   ii = (const int*)d_in[6];
    const int*   jj = (const int*)d_in[7];
    int M = in_sizes[5];                  // b_ids element count
    if (M > MMAX) M = MMAX;

    float* out     = (float*)d_out;
    float* mk0     = out;                 // [M,2]
    float* mk1     = out + 2 * M;         // [M,2]
    float* mconf   = out + 4 * M;         // [M]
    float* conf    = out + 5 * M;         // [M,64,64]

    const int MAIN_SMEM = 4 * 64 * STR * (int)sizeof(float);   // 69632
    const int MLP_SMEM  = 128 * 129 * (int)sizeof(float);      // 66048
    cudaFuncSetAttribute(main_kernel, cudaFuncAttributeMaxDynamicSharedMemorySize, MAIN_SMEM);
    cudaFuncSetAttribute(mlp_kernel,  cudaFuncAttributeMaxDynamicSharedMemorySize, MLP_SMEM);

    prep_kernel<<<16, 256>>>(pw);
    main_kernel<<<M, 256, MAIN_SMEM>>>(f0, f1, conf, mconf);
    mlp_kernel<<<(M + 31) / 32, 256, MLP_SMEM>>>(f0, f1, w1, w2, ii, jj, mk0, mk1, M);
}